// round 1
// baseline (speedup 1.0000x reference)
#include <cuda_runtime.h>

// 7-DOF forward kinematics: propagate (point, z-axis vector) right-to-left
// through the 25-transform chain. Only 2 columns of the 4x4 product are
// needed, so no matrix products at all.

#define DEG 0.017453292519943295f

__global__ void __launch_bounds__(256) fk_kernel(
    const float* __restrict__ thetas,   // [B, 7]
    float* __restrict__ out,            // [B*3 points][B*3 vectors]
    int n)
{
    int i = blockIdx.x * blockDim.x + threadIdx.x;
    if (i >= n) return;

    const float* t = thetas + (long long)i * 7;
    float th0 = t[0], th1 = t[1], th2 = t[2], th3 = t[3];
    float th4 = t[4], th5 = t[5], th6 = t[6];

    // Variable rotation angles (degrees), matching reference exactly
    float a0 = th0;
    float a1 = th1;
    float a2 = -th2;
    float a3 = -th3;
    float a4 = -th4 * 0.5f;
    float a5 = th5 / 4.5f + 10.0f;
    float a6 = 20.0f + (th6 + 180.0f) / 4.5f;

    float s0, c0, s1, c1, s2, c2, s3, c3, s4, c4, s5, c5, s6, c6;
    sincosf(a0 * DEG, &s0, &c0);
    sincosf(a1 * DEG, &s1, &c1);
    sincosf(a2 * DEG, &s2, &c2);
    sincosf(a3 * DEG, &s3, &c3);
    sincosf(a4 * DEG, &s4, &c4);
    sincosf(a5 * DEG, &s5, &c5);
    sincosf(a6 * DEG, &s6, &c6);

    // point p (w=1), vector v (w=0)
    float px = 0.f, py = 0.f, pz = 0.f;
    float vx = 0.f, vy = 0.f, vz = 1.f;

    // Rotation appliers (act on both p and v)
#define ROT_Z(c, s) do { \
        float _x = px, _y = py; px = (c)*_x - (s)*_y; py = (s)*_x + (c)*_y; \
        float _a = vx, _b = vy; vx = (c)*_a - (s)*_b; vy = (s)*_a + (c)*_b; \
    } while (0)
#define ROT_X(c, s) do { \
        float _y = py, _z = pz; py = (c)*_y - (s)*_z; pz = (s)*_y + (c)*_z; \
        float _b = vy, _c2 = vz; vy = (c)*_b - (s)*_c2; vz = (s)*_b + (c)*_c2; \
    } while (0)
#define RY90() do { \
        float _x = px; px = pz; pz = -_x; \
        float _a = vx; vx = vz; vz = -_a; \
    } while (0)
#define RZ90() do { \
        float _x = px; px = -py; py = _x; \
        float _a = vx; vx = -vy; vy = _a; \
    } while (0)
#define RZM90() do { \
        float _x = px; px = py; py = -_x; \
        float _a = vx; vx = vy; vy = -_a; \
    } while (0)
#define RZ180() do { px = -px; py = -py; vx = -vx; vy = -vy; } while (0)
#define RX90() do { \
        float _y = py; py = -pz; pz = _y; \
        float _b = vy; vy = -vz; vz = _b; \
    } while (0)
#define RXM90() do { \
        float _y = py; py = pz; pz = -_y; \
        float _b = vy; vy = vz; vz = -_b; \
    } while (0)

    // Chain applied right-to-left (T25 first)
    RY90();                                   // T25: Ry(90)
    px += 6.0f;                               // T24: Txyz(6,0,0)
    ROT_Z(c6, s6);                            // T23: Rz(a6)
    px += 6.0f;                               // T22: Txyz(6,0,0)
    py += -1.0f;                              // T21: Txyz(0,-1,0)
    ROT_Z(c5, s5);                            // T20: Rz(a5)
    RZM90();                                  // T19: Rz(-90)
    RXM90();                                  // T18: Rx(-90)
    pz += 10.0f;                              // T17: Txyz(0,0,10)
    ROT_Z(c4, s4);                            // T16: Rz(a4)
    RY90();                                   // T15: Ry(90)
    px += 10.0f;                              // T14: Txyz(10,0,0)
    ROT_Z(c3, s3);                            // T13: Rz(a3)
    RZ180();                                  // T12: Rz(180)
    RX90();                                   // T11: Rx(90)
    px += 17.5f;                              // T10: Txyz(17.5,0,0)
    ROT_Z(c2, s2);                            // T9:  Rz(a2)
    RXM90();                                  // T8:  Rx(-90)
    px += 3.0f; pz += 9.5f;                   // T7:  Txyz(3,0,9.5)
    ROT_Z(c1, s1);                            // T6:  Rz(a1)
    RY90();                                   // T5:  Ry(90)
    py += -1.5f; pz += 2.5f;                  // T4:  Txyz(0,-1.5,2.5)
    ROT_Z(c0, s0);                            // T3:  Rz(a0)
    RZ90();                                   // T2:  Rz(90)
    py += 5.0f; pz += 19.5f;                  // T1:  Txyz(0,5,19.5)

    // Output: points [0, 3n), vectors [3n, 6n)
    long long base = (long long)i * 3;
    out[base + 0] = px;
    out[base + 1] = py;
    out[base + 2] = pz;
    long long vbase = (long long)n * 3 + base;
    out[vbase + 0] = vx;
    out[vbase + 1] = vy;
    out[vbase + 2] = vz;
}

extern "C" void kernel_launch(void* const* d_in, const int* in_sizes, int n_in,
                              void* d_out, int out_size)
{
    const float* thetas = (const float*)d_in[0];
    float* out = (float*)d_out;
    int n = in_sizes[0] / 7;   // B
    int threads = 256;
    int blocks = (n + threads - 1) / threads;
    fk_kernel<<<blocks, threads>>>(thetas, out, n);
}

// round 2
// speedup vs baseline: 1.3780x; 1.3780x over previous
#include <cuda_runtime.h>

// 7-DOF forward kinematics: propagate (point, z-axis vector) right-to-left.
// Fast __sincosf (MUFU) path; constant Rz's folded into adjacent variable Rz
// as sign/role swaps of (c,s), so all MUFU args stay < pi (accuracy envelope).

#define DEG 0.017453292519943295f

__global__ void __launch_bounds__(256) fk_kernel(
    const float* __restrict__ thetas,   // [B, 7]
    float* __restrict__ out,            // [B*3 points][B*3 vectors]
    int n)
{
    int i = blockIdx.x * blockDim.x + threadIdx.x;
    if (i >= n) return;

    const float* t = thetas + (long long)i * 7;
    float th0 = t[0], th1 = t[1], th2 = t[2], th3 = t[3];
    float th4 = t[4], th5 = t[5], th6 = t[6];

    // Angles in radians (all in [-1.58, 1.58] -> __sincosf accurate region)
    float r0 = th0 * DEG;                                  // Rz(th0); Rz(90) folded below
    float r1 = th1 * DEG;
    float r2 = th2 * DEG;                                  // chain uses Rz(-th2)
    float r3 = th3 * DEG;                                  // chain uses Rz(180)*Rz(-th3)
    float r4 = th4 * (-0.5f * DEG);
    float r5 = fmaf(th5, DEG / 4.5f, 10.0f * DEG);         // a5 = th5/4.5 + 10; Rz(-90) folded
    float r6 = fmaf(th6, DEG / 4.5f, 60.0f * DEG);         // a6 = 20 + (th6+180)/4.5

    float s0, c0, s1, c1, s2, c2, s3, c3, s4, c4, s5, c5, s6, c6;
    __sincosf(r0, &s0, &c0);
    __sincosf(r1, &s1, &c1);
    __sincosf(r2, &s2, &c2);
    __sincosf(r3, &s3, &c3);
    __sincosf(r4, &s4, &c4);
    __sincosf(r5, &s5, &c5);
    __sincosf(r6, &s6, &c6);

    // point p (w=1), vector v (w=0)
    float px = 0.f, py = 0.f, pz = 0.f;
    float vx = 0.f, vy = 0.f, vz = 1.f;

#define ROT_Z(c, s) do { \
        float _x = px, _y = py; px = (c)*_x - (s)*_y; py = (s)*_x + (c)*_y; \
        float _a = vx, _b = vy; vx = (c)*_a - (s)*_b; vy = (s)*_a + (c)*_b; \
    } while (0)
#define RY90() do { \
        float _x = px; px = pz; pz = -_x; \
        float _a = vx; vx = vz; vz = -_a; \
    } while (0)
#define RX90() do { \
        float _y = py; py = -pz; pz = _y; \
        float _b = vy; vy = -vz; vz = _b; \
    } while (0)
#define RXM90() do { \
        float _y = py; py = pz; pz = -_y; \
        float _b = vy; vy = vz; vz = -_b; \
    } while (0)

    // Chain applied right-to-left (T25 first)
    RY90();                                   // T25: Ry(90)
    px += 6.0f;                               // T24: Txyz(6,0,0)
    ROT_Z(c6, s6);                            // T23: Rz(a6)
    px += 6.0f; py += -1.0f;                  // T22,T21
    ROT_Z(s5, -c5);                           // T20,T19: Rz(-90)*Rz(a5) = Rz(a5-90)
    RXM90();                                  // T18: Rx(-90)
    pz += 10.0f;                              // T17
    ROT_Z(c4, s4);                            // T16: Rz(-th4/2)
    RY90();                                   // T15: Ry(90)
    px += 10.0f;                              // T14
    ROT_Z(-c3, s3);                           // T13,T12: Rz(180)*Rz(-th3) = Rz(180-th3)
    RX90();                                   // T11: Rx(90)
    px += 17.5f;                              // T10
    ROT_Z(c2, -s2);                           // T9:  Rz(-th2)
    RXM90();                                  // T8:  Rx(-90)
    px += 3.0f; pz += 9.5f;                   // T7
    ROT_Z(c1, s1);                            // T6:  Rz(th1)
    RY90();                                   // T5:  Ry(90)
    py += -1.5f; pz += 2.5f;                  // T4
    ROT_Z(-s0, c0);                           // T3,T2: Rz(90)*Rz(th0) = Rz(th0+90)
    py += 5.0f; pz += 19.5f;                  // T1

    long long base = (long long)i * 3;
    out[base + 0] = px;
    out[base + 1] = py;
    out[base + 2] = pz;
    long long vbase = (long long)n * 3 + base;
    out[vbase + 0] = vx;
    out[vbase + 1] = vy;
    out[vbase + 2] = vz;
}

extern "C" void kernel_launch(void* const* d_in, const int* in_sizes, int n_in,
                              void* d_out, int out_size)
{
    const float* thetas = (const float*)d_in[0];
    float* out = (float*)d_out;
    int n = in_sizes[0] / 7;   // B
    int threads = 256;
    int blocks = (n + threads - 1) / threads;
    fk_kernel<<<blocks, threads>>>(thetas, out, n);
}